// round 11
// baseline (speedup 1.0000x reference)
#include <cuda_runtime.h>
#include <cstdint>

#define D_DIM   768
#define ROW_B   (D_DIM * 4)          // 3072 bytes per row
#define F4_ROW  (D_DIM / 4)          // 192
#define F4_LANE 6                    // float4 per lane
#define WARPS   4
#define NTHR    (WARPS * 32)         // 128
#define NSTAGE  4                    // smem ring depth per warp
#define RPW     8                    // rows per warp
#define LN_EPS  1e-6f

// dynamic smem layout (bytes)
#define SM_STAGE  0
#define SM_G      (WARPS * NSTAGE * ROW_B)           // 49152
#define SM_BE     (SM_G + ROW_B)                     // 52224
#define SM_MBAR   (SM_BE + ROW_B)                    // 55296
#define SM_TOTAL  (SM_MBAR + WARPS * NSTAGE * 8)     // 55424

__device__ __forceinline__ void mbar_init(unsigned mbar, unsigned cnt) {
    asm volatile("mbarrier.init.shared.b64 [%0], %1;" :: "r"(mbar), "r"(cnt) : "memory");
}
__device__ __forceinline__ void mbar_expect_tx(unsigned mbar, unsigned bytes) {
    asm volatile("mbarrier.arrive.expect_tx.shared.b64 _, [%0], %1;" :: "r"(mbar), "r"(bytes) : "memory");
}
__device__ __forceinline__ void bulk_g2s(unsigned dst, const void* src, unsigned bytes, unsigned mbar) {
    asm volatile(
        "cp.async.bulk.shared::cta.global.mbarrier::complete_tx::bytes [%0], [%1], %2, [%3];"
        :: "r"(dst), "l"(src), "r"(bytes), "r"(mbar) : "memory");
}
__device__ __forceinline__ void mbar_wait(unsigned mbar, unsigned phase) {
    asm volatile(
        "{\n\t"
        ".reg .pred P;\n\t"
        "WAIT_%=:\n\t"
        "mbarrier.try_wait.parity.acquire.cta.shared::cta.b64 P, [%0], %1, 0x989680;\n\t"
        "@P bra.uni DONE_%=;\n\t"
        "bra.uni WAIT_%=;\n\t"
        "DONE_%=:\n\t"
        "}"
        :: "r"(mbar), "r"(phase) : "memory");
}

__global__ __launch_bounds__(NTHR, 4)
void hier_attn_ln_kernel(const int*   __restrict__ ids,
                         const float* __restrict__ pooler,
                         const float* __restrict__ emb,     // (V,2)
                         const float* __restrict__ Wd,      // (2,D)
                         const float* __restrict__ bd,      // (D)
                         const float* __restrict__ gamma,   // (D)
                         const float* __restrict__ beta,    // (D)
                         float*       __restrict__ out,
                         int L)
{
    extern __shared__ unsigned char sm[];
    float4* sG  = reinterpret_cast<float4*>(sm + SM_G);
    float4* sBE = reinterpret_cast<float4*>(sm + SM_BE);
    const unsigned smBase = (unsigned)__cvta_generic_to_shared(sm);

    const int b    = blockIdx.y;
    const int warp = threadIdx.x >> 5;
    const int lane = threadIdx.x & 31;
    const int t    = threadIdx.x;

    // ---- init mbarriers (count=1: one arrive.expect_tx per phase) ----
    if (t < WARPS * NSTAGE)
        mbar_init(smBase + SM_MBAR + t * 8, 1);
    asm volatile("fence.proxy.async.shared::cta;" ::: "memory");

    // ---- stage gamma/beta into smem ----
    {
        const float4* GG = reinterpret_cast<const float4*>(gamma);
        const float4* BE = reinterpret_cast<const float4*>(beta);
        #pragma unroll
        for (int i = t; i < F4_ROW; i += NTHR) {
            sG [i] = GG[i];
            sBE[i] = BE[i];
        }
    }

    // ---- per-warp x vector in registers; Sx/xx reduced within the warp ----
    const int   id = __ldg(ids + b);
    const float e0 = __ldg(emb + 2 * id);
    const float e1 = __ldg(emb + 2 * id + 1);

    const float4* W0 = reinterpret_cast<const float4*>(Wd);
    const float4* W1 = reinterpret_cast<const float4*>(Wd + D_DIM);
    const float4* BB = reinterpret_cast<const float4*>(bd);

    float4 xv[F4_LANE];
    float Sx = 0.f, xx = 0.f;
    #pragma unroll
    for (int j = 0; j < F4_LANE; ++j) {
        const int c = lane + 32 * j;
        float4 w0 = W0[c], w1 = W1[c], bb = BB[c];
        float4 v;
        v.x = fmaf(e0, w0.x, fmaf(e1, w1.x, bb.x));
        v.y = fmaf(e0, w0.y, fmaf(e1, w1.y, bb.y));
        v.z = fmaf(e0, w0.z, fmaf(e1, w1.z, bb.z));
        v.w = fmaf(e0, w0.w, fmaf(e1, w1.w, bb.w));
        xv[j] = v;
        Sx += v.x + v.y + v.z + v.w;
        xx = fmaf(v.x, v.x, fmaf(v.y, v.y, fmaf(v.z, v.z, fmaf(v.w, v.w, xx))));
    }
    #pragma unroll
    for (int off = 16; off > 0; off >>= 1) {
        Sx += __shfl_xor_sync(0xffffffffu, Sx, off);
        xx += __shfl_xor_sync(0xffffffffu, xx, off);
    }

    __syncthreads();   // barriers initialized + gamma/beta staged

    const int l0 = (blockIdx.x * WARPS + warp) * RPW;
    if (l0 >= L) return;
    const int nrows = min(RPW, L - l0);

    const float invD = 1.0f / (float)D_DIM;
    const float* rowPtr = pooler + ((size_t)b * L + l0) * D_DIM;
    float*       outPtr = out    + ((size_t)b * L + l0) * D_DIM;

    const unsigned stage0 = smBase + SM_STAGE + warp * (NSTAGE * ROW_B);
    const unsigned mbar0  = smBase + SM_MBAR  + warp * (NSTAGE * 8);

    // ---- fill the ring: issue first NSTAGE bulk copies ----
    if (lane == 0) {
        #pragma unroll
        for (int s = 0; s < NSTAGE; ++s) {
            if (s < nrows) {
                mbar_expect_tx(mbar0 + s * 8, ROW_B);
                bulk_g2s(stage0 + s * ROW_B, rowPtr + (size_t)s * D_DIM, ROW_B, mbar0 + s * 8);
            }
        }
    }

    #pragma unroll
    for (int r = 0; r < RPW; ++r) {
        if (r >= nrows) break;
        const int s = r & (NSTAGE - 1);
        const unsigned ph = (r >> 2) & 1;

        // wait for this row's data
        mbar_wait(mbar0 + s * 8, ph);

        // consume stage into registers
        const float4* sp = reinterpret_cast<const float4*>(sm + (warp * NSTAGE + s) * ROW_B);
        float4 p[F4_LANE];
        #pragma unroll
        for (int j = 0; j < F4_LANE; ++j)
            p[j] = sp[lane + 32 * j];

        __syncwarp();   // all lanes done reading the stage

        // refill the stage with row r+NSTAGE (before the long chain)
        if (lane == 0 && r + NSTAGE < nrows) {
            mbar_expect_tx(mbar0 + s * 8, ROW_B);
            bulk_g2s(stage0 + s * ROW_B, rowPtr + (size_t)(r + NSTAGE) * D_DIM, ROW_B, mbar0 + s * 8);
        }

        // partials (split accumulators)
        float pp0 = 0.f, pp1 = 0.f, px0 = 0.f, px1 = 0.f, Sp0 = 0.f, Sp1 = 0.f;
        #pragma unroll
        for (int j = 0; j < F4_LANE; j += 2) {
            pp0 = fmaf(p[j].x, p[j].x,  fmaf(p[j].y, p[j].y,  fmaf(p[j].z, p[j].z,  fmaf(p[j].w, p[j].w,  pp0))));
            px0 = fmaf(p[j].x, xv[j].x, fmaf(p[j].y, xv[j].y, fmaf(p[j].z, xv[j].z, fmaf(p[j].w, xv[j].w, px0))));
            Sp0 += p[j].x + p[j].y + p[j].z + p[j].w;
            const int k = j + 1;
            pp1 = fmaf(p[k].x, p[k].x,  fmaf(p[k].y, p[k].y,  fmaf(p[k].z, p[k].z,  fmaf(p[k].w, p[k].w,  pp1))));
            px1 = fmaf(p[k].x, xv[k].x, fmaf(p[k].y, xv[k].y, fmaf(p[k].z, xv[k].z, fmaf(p[k].w, xv[k].w, px1))));
            Sp1 += p[k].x + p[k].y + p[k].z + p[k].w;
        }
        float pp = pp0 + pp1, px = px0 + px1, Sp = Sp0 + Sp1;

        // butterfly reduction
        #pragma unroll
        for (int off = 16; off > 0; off >>= 1) {
            pp += __shfl_xor_sync(0xffffffffu, pp, off);
            px += __shfl_xor_sync(0xffffffffu, px, off);
            Sp += __shfl_xor_sync(0xffffffffu, Sp, off);
        }

        // softmax weights via sigmoids: wp = sig(pp-px) + sig(px-xx); wx = 2 - wp
        float wp = __fdividef(1.f, 1.f + __expf(px - pp))
                 + __fdividef(1.f, 1.f + __expf(xx - px));
        float wx = 2.0f - wp;

        // analytic layernorm stats of summed = wp*p + wx*x
        float mean = (wp * Sp + wx * Sx) * invD;
        float ss2  = wp*wp*pp + 2.0f*wp*wx*px + wx*wx*xx;
        float inv  = rsqrtf(ss2 * invD - mean * mean + LN_EPS);
        float cwp  = wp * inv;
        float cwx  = wx * inv;
        float ncm  = -mean * inv;

        // o = g * (cwp*p + cwx*x + ncm) + beta
        float4* orow = reinterpret_cast<float4*>(outPtr + (size_t)r * D_DIM);
        #pragma unroll
        for (int j = 0; j < F4_LANE; ++j) {
            const int c = lane + 32 * j;
            const float4 g  = sG[c];
            const float4 be = sBE[c];
            float4 o;
            o.x = fmaf(fmaf(cwp, p[j].x, fmaf(cwx, xv[j].x, ncm)), g.x, be.x);
            o.y = fmaf(fmaf(cwp, p[j].y, fmaf(cwx, xv[j].y, ncm)), g.y, be.y);
            o.z = fmaf(fmaf(cwp, p[j].z, fmaf(cwx, xv[j].z, ncm)), g.z, be.z);
            o.w = fmaf(fmaf(cwp, p[j].w, fmaf(cwx, xv[j].w, ncm)), g.w, be.w);
            __stcs(orow + c, o);
        }
    }
}

extern "C" void kernel_launch(void* const* d_in, const int* in_sizes, int n_in,
                              void* d_out, int out_size)
{
    const int*   ids    = (const int*)  d_in[0];
    const float* pooler = (const float*)d_in[1];
    const float* emb    = (const float*)d_in[2];
    const float* Wd     = (const float*)d_in[3];
    const float* bd     = (const float*)d_in[4];
    const float* gamma  = (const float*)d_in[5];
    const float* beta   = (const float*)d_in[6];
    float* out = (float*)d_out;

    const int B = in_sizes[0];                      // ids is (B,1)
    const int L = in_sizes[1] / (B * D_DIM);        // pooler is (B,L,D)

    static bool attr_set = false;
    if (!attr_set) {
        cudaFuncSetAttribute(hier_attn_ln_kernel,
                             cudaFuncAttributeMaxDynamicSharedMemorySize, SM_TOTAL);
        attr_set = true;
    }

    dim3 grid((L + WARPS * RPW - 1) / (WARPS * RPW), B);
    hier_attn_ln_kernel<<<grid, NTHR, SM_TOTAL>>>(ids, pooler, emb, Wd, bd, gamma, beta, out, L);
}

// round 12
// speedup vs baseline: 1.0539x; 1.0539x over previous
#include <cuda_runtime.h>
#include <cstdint>

#define D_DIM    768
#define ROW_B    (D_DIM * 4)          // 3072 bytes per row
#define F4_ROW   (D_DIM / 4)          // 192
#define F4_LANE  6                    // float4 per lane
#define NCONS    8                    // consumer warps
#define NWARP    (NCONS + 1)          // + 1 producer warp
#define NTHR     (NWARP * 32)         // 288
#define NSTAGE   16                   // smem ring depth (2 phases of 16)
#define BLKROWS  32                   // rows per block
#define LN_EPS   1e-6f

// dynamic smem layout (bytes)
#define SM_STAGE  0
#define SM_X      (NSTAGE * ROW_B)                   // 49152
#define SM_G      (SM_X  + ROW_B)                    // 52224
#define SM_BE     (SM_G  + ROW_B)                    // 55296
#define SM_MBAR   (SM_BE + ROW_B)                    // 58368  (16 full + 16 empty)
#define SM_RED    (SM_MBAR + NSTAGE * 16)            // 58624
#define SM_TOTAL  (SM_RED + NWARP * 2 * 4 + 16)      // ~58712

__device__ __forceinline__ void mbar_init(unsigned mbar, unsigned cnt) {
    asm volatile("mbarrier.init.shared.b64 [%0], %1;" :: "r"(mbar), "r"(cnt) : "memory");
}
__device__ __forceinline__ void mbar_expect_tx(unsigned mbar, unsigned bytes) {
    asm volatile("mbarrier.arrive.expect_tx.shared.b64 _, [%0], %1;" :: "r"(mbar), "r"(bytes) : "memory");
}
__device__ __forceinline__ void mbar_arrive(unsigned mbar) {
    asm volatile("mbarrier.arrive.release.cta.shared.b64 _, [%0];" :: "r"(mbar) : "memory");
}
__device__ __forceinline__ void bulk_g2s(unsigned dst, const void* src, unsigned bytes, unsigned mbar) {
    asm volatile(
        "cp.async.bulk.shared::cta.global.mbarrier::complete_tx::bytes [%0], [%1], %2, [%3];"
        :: "r"(dst), "l"(src), "r"(bytes), "r"(mbar) : "memory");
}
__device__ __forceinline__ void mbar_wait(unsigned mbar, unsigned phase) {
    asm volatile(
        "{\n\t"
        ".reg .pred P;\n\t"
        "WAIT_%=:\n\t"
        "mbarrier.try_wait.parity.acquire.cta.shared::cta.b64 P, [%0], %1, 0x989680;\n\t"
        "@P bra.uni DONE_%=;\n\t"
        "bra.uni WAIT_%=;\n\t"
        "DONE_%=:\n\t"
        "}"
        :: "r"(mbar), "r"(phase) : "memory");
}

__global__ __launch_bounds__(NTHR, 2)
void hier_attn_ln_kernel(const int*   __restrict__ ids,
                         const float* __restrict__ pooler,
                         const float* __restrict__ emb,     // (V,2)
                         const float* __restrict__ Wd,      // (2,D)
                         const float* __restrict__ bd,      // (D)
                         const float* __restrict__ gamma,   // (D)
                         const float* __restrict__ beta,    // (D)
                         float*       __restrict__ out,
                         int L)
{
    extern __shared__ unsigned char sm[];
    float4* sX  = reinterpret_cast<float4*>(sm + SM_X);
    float4* sG  = reinterpret_cast<float4*>(sm + SM_G);
    float4* sBE = reinterpret_cast<float4*>(sm + SM_BE);
    float*  sred = reinterpret_cast<float*>(sm + SM_RED);
    const unsigned smBase = (unsigned)__cvta_generic_to_shared(sm);
    const unsigned mbFull  = smBase + SM_MBAR;               // 16 x 8B
    const unsigned mbEmpty = smBase + SM_MBAR + NSTAGE * 8;  // 16 x 8B

    const int b    = blockIdx.y;
    const int warp = threadIdx.x >> 5;
    const int lane = threadIdx.x & 31;
    const int t    = threadIdx.x;

    // ---- init mbarriers ----
    if (t < NSTAGE) {
        mbar_init(mbFull  + t * 8, 1);   // TMA tx completion
        mbar_init(mbEmpty + t * 8, 1);   // one consumer arrive
    }
    asm volatile("fence.proxy.async.shared::cta;" ::: "memory");

    // ---- block prologue: x, gamma, beta into smem; reduce Sx, xx ----
    const int   id = __ldg(ids + b);
    const float e0 = __ldg(emb + 2 * id);
    const float e1 = __ldg(emb + 2 * id + 1);

    float sxp = 0.f, xxp = 0.f;
    if (t < F4_ROW) {
        float4 w0 = reinterpret_cast<const float4*>(Wd)[t];
        float4 w1 = reinterpret_cast<const float4*>(Wd + D_DIM)[t];
        float4 bb = reinterpret_cast<const float4*>(bd)[t];
        float4 v;
        v.x = fmaf(e0, w0.x, fmaf(e1, w1.x, bb.x));
        v.y = fmaf(e0, w0.y, fmaf(e1, w1.y, bb.y));
        v.z = fmaf(e0, w0.z, fmaf(e1, w1.z, bb.z));
        v.w = fmaf(e0, w0.w, fmaf(e1, w1.w, bb.w));
        sX [t] = v;
        sG [t] = reinterpret_cast<const float4*>(gamma)[t];
        sBE[t] = reinterpret_cast<const float4*>(beta)[t];
        sxp = v.x + v.y + v.z + v.w;
        xxp = fmaf(v.x, v.x, fmaf(v.y, v.y, fmaf(v.z, v.z, v.w * v.w)));
    }
    #pragma unroll
    for (int off = 16; off > 0; off >>= 1) {
        sxp += __shfl_xor_sync(0xffffffffu, sxp, off);
        xxp += __shfl_xor_sync(0xffffffffu, xxp, off);
    }
    if (lane == 0) { sred[warp * 2] = sxp; sred[warp * 2 + 1] = xxp; }
    __syncthreads();

    float Sx = 0.f, xx = 0.f;
    #pragma unroll
    for (int w = 0; w < NWARP; ++w) { Sx += sred[w * 2]; xx += sred[w * 2 + 1]; }

    const int l0    = blockIdx.x * BLKROWS;
    const int nrows = min(BLKROWS, L - l0);
    const float* rowPtr = pooler + ((size_t)b * L + l0) * D_DIM;
    float*       outPtr = out    + ((size_t)b * L + l0) * D_DIM;

    if (warp == NCONS) {
        // ================= PRODUCER WARP =================
        if (lane == 0) {
            for (int r = 0; r < nrows; ++r) {
                const int s = r & (NSTAGE - 1);
                const int k = r >> 4;                 // ring round
                if (k > 0)
                    mbar_wait(mbEmpty + s * 8, (k - 1) & 1);
                mbar_expect_tx(mbFull + s * 8, ROW_B);
                bulk_g2s(smBase + SM_STAGE + s * ROW_B,
                         rowPtr + (size_t)r * D_DIM, ROW_B, mbFull + s * 8);
            }
        }
    } else {
        // ================= CONSUMER WARPS =================
        const float invD = 1.0f / (float)D_DIM;

        // x vector into registers (once per warp)
        float4 xv[F4_LANE];
        #pragma unroll
        for (int j = 0; j < F4_LANE; ++j)
            xv[j] = sX[lane + 32 * j];

        for (int r = warp; r < nrows; r += NCONS) {
            const int s = r & (NSTAGE - 1);
            const int k = r >> 4;

            mbar_wait(mbFull + s * 8, k & 1);

            const float4* sp = reinterpret_cast<const float4*>(sm + SM_STAGE + s * ROW_B);
            float4 p[F4_LANE];
            #pragma unroll
            for (int j = 0; j < F4_LANE; ++j)
                p[j] = sp[lane + 32 * j];

            __syncwarp();
            if (lane == 0) mbar_arrive(mbEmpty + s * 8);   // slot free for refill

            // partials (split accumulators)
            float pp0 = 0.f, pp1 = 0.f, px0 = 0.f, px1 = 0.f, Sp0 = 0.f, Sp1 = 0.f;
            #pragma unroll
            for (int j = 0; j < F4_LANE; j += 2) {
                pp0 = fmaf(p[j].x, p[j].x,  fmaf(p[j].y, p[j].y,  fmaf(p[j].z, p[j].z,  fmaf(p[j].w, p[j].w,  pp0))));
                px0 = fmaf(p[j].x, xv[j].x, fmaf(p[j].y, xv[j].y, fmaf(p[j].z, xv[j].z, fmaf(p[j].w, xv[j].w, px0))));
                Sp0 += p[j].x + p[j].y + p[j].z + p[j].w;
                const int q = j + 1;
                pp1 = fmaf(p[q].x, p[q].x,  fmaf(p[q].y, p[q].y,  fmaf(p[q].z, p[q].z,  fmaf(p[q].w, p[q].w,  pp1))));
                px1 = fmaf(p[q].x, xv[q].x, fmaf(p[q].y, xv[q].y, fmaf(p[q].z, xv[q].z, fmaf(p[q].w, xv[q].w, px1))));
                Sp1 += p[q].x + p[q].y + p[q].z + p[q].w;
            }
            float pp = pp0 + pp1, px = px0 + px1, Sp = Sp0 + Sp1;

            #pragma unroll
            for (int off = 16; off > 0; off >>= 1) {
                pp += __shfl_xor_sync(0xffffffffu, pp, off);
                px += __shfl_xor_sync(0xffffffffu, px, off);
                Sp += __shfl_xor_sync(0xffffffffu, Sp, off);
            }

            // softmax weights via sigmoids: wp = sig(pp-px) + sig(px-xx); wx = 2-wp
            float wp = __fdividef(1.f, 1.f + __expf(px - pp))
                     + __fdividef(1.f, 1.f + __expf(xx - px));
            float wx = 2.0f - wp;

            // analytic layernorm stats of summed = wp*p + wx*x
            float mean = (wp * Sp + wx * Sx) * invD;
            float ss2  = wp*wp*pp + 2.0f*wp*wx*px + wx*wx*xx;
            float inv  = rsqrtf(ss2 * invD - mean * mean + LN_EPS);
            float cwp  = wp * inv;
            float cwx  = wx * inv;
            float ncm  = -mean * inv;

            float4* orow = reinterpret_cast<float4*>(outPtr + (size_t)r * D_DIM);
            #pragma unroll
            for (int j = 0; j < F4_LANE; ++j) {
                const int c = lane + 32 * j;
                const float4 g  = sG[c];
                const float4 be = sBE[c];
                float4 o;
                o.x = fmaf(fmaf(cwp, p[j].x, fmaf(cwx, xv[j].x, ncm)), g.x, be.x);
                o.y = fmaf(fmaf(cwp, p[j].y, fmaf(cwx, xv[j].y, ncm)), g.y, be.y);
                o.z = fmaf(fmaf(cwp, p[j].z, fmaf(cwx, xv[j].z, ncm)), g.z, be.z);
                o.w = fmaf(fmaf(cwp, p[j].w, fmaf(cwx, xv[j].w, ncm)), g.w, be.w);
                __stcs(orow + c, o);
            }
        }
    }
}

extern "C" void kernel_launch(void* const* d_in, const int* in_sizes, int n_in,
                              void* d_out, int out_size)
{
    const int*   ids    = (const int*)  d_in[0];
    const float* pooler = (const float*)d_in[1];
    const float* emb    = (const float*)d_in[2];
    const float* Wd     = (const float*)d_in[3];
    const float* bd     = (const float*)d_in[4];
    const float* gamma  = (const float*)d_in[5];
    const float* beta   = (const float*)d_in[6];
    float* out = (float*)d_out;

    const int B = in_sizes[0];                      // ids is (B,1)
    const int L = in_sizes[1] / (B * D_DIM);        // pooler is (B,L,D)

    static bool attr_set = false;
    if (!attr_set) {
        cudaFuncSetAttribute(hier_attn_ln_kernel,
                             cudaFuncAttributeMaxDynamicSharedMemorySize, SM_TOTAL);
        attr_set = true;
    }

    dim3 grid((L + BLKROWS - 1) / BLKROWS, B);
    hier_attn_ln_kernel<<<grid, NTHR, SM_TOTAL>>>(ids, pooler, emb, Wd, bd, gamma, beta, out, L);
}